// round 1
// baseline (speedup 1.0000x reference)
#include <cuda_runtime.h>
#include <math.h>

#define TOK    1568          // D*H*W = 8*14*14
#define BATCH  4
#define CDIM   768
#define TTOK   (BATCH*TOK)   // 6272
#define QKVDIM 2304
#define HID    3072
#define NHEAD  12
#define DHEAD  64

// ---------------- scratch (device globals: no allocation allowed) ----------------
__device__ float g_t[TTOK * CDIM];     // token residual stream [T, C]
__device__ float g_h[TTOK * CDIM];     // LN output
__device__ float g_qkv[TTOK * QKVDIM]; // qkv projection
__device__ float g_o[TTOK * CDIM];     // attention output
__device__ float g_mlp[TTOK * HID];    // fc1 output

// ---------------- depthwise 3x3x3 conv + bias + residual + tokenize ----------------
// one block per (b, c); writes g_t[(b*TOK+s)*C + c] = x + conv(x) + pos_b[c]
__global__ void conv_pos_kernel(const float* __restrict__ x,
                                const float* __restrict__ pw,
                                const float* __restrict__ pb) {
    int bc = blockIdx.x;          // b*CDIM + c
    int c  = bc % CDIM;
    int b  = bc / CDIM;
    __shared__ float sx[TOK];
    __shared__ float sw[27];
    int tid = threadIdx.x;
    const float* xs = x + (size_t)bc * TOK;
    for (int i = tid; i < TOK; i += 256) sx[i] = xs[i];
    if (tid < 27) sw[tid] = pw[c * 27 + tid];
    __syncthreads();
    float pbv = pb[c];
    for (int idx = tid; idx < TOK; idx += 256) {
        int d = idx / 196; int r = idx - d * 196;
        int h = r / 14;    int w = r - h * 14;
        float acc = 0.f;
        #pragma unroll
        for (int kd = 0; kd < 3; kd++) {
            int dd = d + kd - 1;
            if (dd < 0 || dd >= 8) continue;
            #pragma unroll
            for (int kh = 0; kh < 3; kh++) {
                int hh = h + kh - 1;
                if (hh < 0 || hh >= 14) continue;
                #pragma unroll
                for (int kw = 0; kw < 3; kw++) {
                    int ww = w + kw - 1;
                    if (ww < 0 || ww >= 14) continue;
                    acc += sw[kd * 9 + kh * 3 + kw] * sx[dd * 196 + hh * 14 + ww];
                }
            }
        }
        g_t[(size_t)(b * TOK + idx) * CDIM + c] = sx[idx] + acc + pbv;
    }
}

// ---------------- LayerNorm: one block (256 thr) per token, C=768 ----------------
__global__ void ln_kernel(const float* __restrict__ in, const float* __restrict__ w,
                          const float* __restrict__ bsrc, float* __restrict__ out) {
    int t = blockIdx.x;
    int tid = threadIdx.x;
    const float* row = in + (size_t)t * CDIM;
    float v0 = row[tid], v1 = row[tid + 256], v2 = row[tid + 512];
    float s  = v0 + v1 + v2;
    float sq = v0 * v0 + v1 * v1 + v2 * v2;
    #pragma unroll
    for (int off = 16; off; off >>= 1) {
        s  += __shfl_xor_sync(0xffffffffu, s,  off);
        sq += __shfl_xor_sync(0xffffffffu, sq, off);
    }
    __shared__ float ss[8], ssq[8];
    int wid = tid >> 5, lid = tid & 31;
    if (lid == 0) { ss[wid] = s; ssq[wid] = sq; }
    __syncthreads();
    if (tid < 32) {
        s  = (lid < 8) ? ss[lid]  : 0.f;
        sq = (lid < 8) ? ssq[lid] : 0.f;
        #pragma unroll
        for (int off = 4; off; off >>= 1) {
            s  += __shfl_xor_sync(0xffffffffu, s,  off);
            sq += __shfl_xor_sync(0xffffffffu, sq, off);
        }
        if (lid == 0) { ss[0] = s; ssq[0] = sq; }
    }
    __syncthreads();
    float mean = ss[0] * (1.f / CDIM);
    float var  = ssq[0] * (1.f / CDIM) - mean * mean;
    float rs   = rsqrtf(var + 1e-5f);
    float* orow = out + (size_t)t * CDIM;
    orow[tid]       = (v0 - mean) * rs * w[tid]       + bsrc[tid];
    orow[tid + 256] = (v1 - mean) * rs * w[tid + 256] + bsrc[tid + 256];
    orow[tid + 512] = (v2 - mean) * rs * w[tid + 512] + bsrc[tid + 512];
}

// ---------------- GEMM: C[M,N] = A[M,K] @ B[N,K]^T (+epilogue) ----------------
// 128x128 block tile, BK=16, 256 threads, 8x8 microtile.
// MODE 0: C = acc ; MODE 1: C = resid + bias + acc ; MODE 2: C = gelu(acc + bias)
__device__ __forceinline__ float gelu_exact(float v) {
    return 0.5f * v * (1.f + erff(v * 0.70710678118654752f));
}

template <int MODE>
__global__ void __launch_bounds__(256)
gemm128(const float* __restrict__ A, const float* __restrict__ B,
        const float* __restrict__ bias, const float* __restrict__ resid,
        float* __restrict__ C, int M, int N, int K) {
    __shared__ __align__(16) float As[16][132];
    __shared__ __align__(16) float Bs[16][132];
    int tid = threadIdx.x;
    int tr = tid >> 4, tc = tid & 15;
    int m0 = blockIdx.y << 7, n0 = blockIdx.x << 7;
    const float* Ab = A + (size_t)m0 * K;
    const float* Bb = B + (size_t)n0 * K;
    float acc[8][8];
    #pragma unroll
    for (int i = 0; i < 8; i++)
        #pragma unroll
        for (int j = 0; j < 8; j++) acc[i][j] = 0.f;

    for (int k0 = 0; k0 < K; k0 += 16) {
        #pragma unroll
        for (int r = 0; r < 2; r++) {
            int idx = tid + (r << 8);   // 0..511
            int row = idx >> 2;
            int kq  = (idx & 3) << 2;
            float4 a = *(const float4*)(Ab + (size_t)row * K + k0 + kq);
            As[kq + 0][row] = a.x; As[kq + 1][row] = a.y;
            As[kq + 2][row] = a.z; As[kq + 3][row] = a.w;
            float4 bb = *(const float4*)(Bb + (size_t)row * K + k0 + kq);
            Bs[kq + 0][row] = bb.x; Bs[kq + 1][row] = bb.y;
            Bs[kq + 2][row] = bb.z; Bs[kq + 3][row] = bb.w;
        }
        __syncthreads();
        #pragma unroll
        for (int k = 0; k < 16; k++) {
            float av[8], bv[8];
            *(float4*)(av)     = *(const float4*)&As[k][tr * 8];
            *(float4*)(av + 4) = *(const float4*)&As[k][tr * 8 + 4];
            *(float4*)(bv)     = *(const float4*)&Bs[k][tc * 8];
            *(float4*)(bv + 4) = *(const float4*)&Bs[k][tc * 8 + 4];
            #pragma unroll
            for (int i = 0; i < 8; i++)
                #pragma unroll
                for (int j = 0; j < 8; j++)
                    acc[i][j] = fmaf(av[i], bv[j], acc[i][j]);
        }
        __syncthreads();
    }

    #pragma unroll
    for (int i = 0; i < 8; i++) {
        int m = m0 + tr * 8 + i;
        #pragma unroll
        for (int jj = 0; jj < 2; jj++) {
            int n = n0 + tc * 8 + jj * 4;
            float4 r;
            r.x = acc[i][jj * 4 + 0]; r.y = acc[i][jj * 4 + 1];
            r.z = acc[i][jj * 4 + 2]; r.w = acc[i][jj * 4 + 3];
            if (MODE == 1) {
                float4 bv = *(const float4*)(bias + n);
                float4 rv = *(const float4*)(resid + (size_t)m * N + n);
                r.x += bv.x + rv.x; r.y += bv.y + rv.y;
                r.z += bv.z + rv.z; r.w += bv.w + rv.w;
            } else if (MODE == 2) {
                float4 bv = *(const float4*)(bias + n);
                r.x = gelu_exact(r.x + bv.x); r.y = gelu_exact(r.y + bv.y);
                r.z = gelu_exact(r.z + bv.z); r.w = gelu_exact(r.w + bv.w);
            }
            *(float4*)(C + (size_t)m * N + n) = r;
        }
    }
}

// ---------------- Flash attention: block = (64 queries) x (b,h) ----------------
// 256 threads as 16x16; each thread: 4x4 S microtile, 4x4 O microtile.
// K smem buffer is reused for P after S is consumed; V loaded in 32-row halves.
__global__ void __launch_bounds__(256)
attn_kernel(const float* __restrict__ qkv, float* __restrict__ o) {
    __shared__ __align__(16) float Qs[64][65];
    __shared__ __align__(16) float KPs[64][65];
    __shared__ __align__(16) float Vs[32][64];
    int tid = threadIdx.x;
    int ty = tid >> 4, tx = tid & 15;
    int bh = blockIdx.y;
    int b = bh / NHEAD, h = bh % NHEAD;
    int q0 = blockIdx.x * 64;

    // load Q tile (scale folded in)
    for (int i = tid; i < 1024; i += 256) {
        int row = i >> 4; int c4 = (i & 15) << 2;
        int q = q0 + row;
        float4 v = make_float4(0.f, 0.f, 0.f, 0.f);
        if (q < TOK)
            v = *(const float4*)(qkv + (size_t)(b * TOK + q) * QKVDIM + h * DHEAD + c4);
        Qs[row][c4 + 0] = v.x * 0.125f; Qs[row][c4 + 1] = v.y * 0.125f;
        Qs[row][c4 + 2] = v.z * 0.125f; Qs[row][c4 + 3] = v.w * 0.125f;
    }

    float oacc[4][4];
    float m_i[4], l_i[4];
    #pragma unroll
    for (int qi = 0; qi < 4; qi++) {
        m_i[qi] = -1e30f; l_i[qi] = 0.f;
        #pragma unroll
        for (int di = 0; di < 4; di++) oacc[qi][di] = 0.f;
    }

    const int nkc = (TOK + 63) / 64;    // 25
    for (int kc = 0; kc < nkc; kc++) {
        // load K tile
        for (int i = tid; i < 1024; i += 256) {
            int row = i >> 4; int c4 = (i & 15) << 2;
            int key = kc * 64 + row;
            float4 v = make_float4(0.f, 0.f, 0.f, 0.f);
            if (key < TOK)
                v = *(const float4*)(qkv + (size_t)(b * TOK + key) * QKVDIM + CDIM + h * DHEAD + c4);
            KPs[row][c4 + 0] = v.x; KPs[row][c4 + 1] = v.y;
            KPs[row][c4 + 2] = v.z; KPs[row][c4 + 3] = v.w;
        }
        __syncthreads();

        // S = Q K^T  (64x64, thread owns 4x4)
        float s[4][4];
        #pragma unroll
        for (int qi = 0; qi < 4; qi++)
            #pragma unroll
            for (int ki = 0; ki < 4; ki++) s[qi][ki] = 0.f;
        #pragma unroll 4
        for (int d = 0; d < 64; d++) {
            float qv[4], kv[4];
            #pragma unroll
            for (int qi = 0; qi < 4; qi++) qv[qi] = Qs[ty * 4 + qi][d];
            #pragma unroll
            for (int ki = 0; ki < 4; ki++) kv[ki] = KPs[tx * 4 + ki][d];
            #pragma unroll
            for (int qi = 0; qi < 4; qi++)
                #pragma unroll
                for (int ki = 0; ki < 4; ki++)
                    s[qi][ki] = fmaf(qv[qi], kv[ki], s[qi][ki]);
        }
        // mask OOB keys (last chunk only)
        #pragma unroll
        for (int ki = 0; ki < 4; ki++) {
            if (kc * 64 + tx * 4 + ki >= TOK) {
                #pragma unroll
                for (int qi = 0; qi < 4; qi++) s[qi][ki] = -1e30f;
            }
        }
        // online softmax update (row = query; 16 tx lanes per row)
        #pragma unroll
        for (int qi = 0; qi < 4; qi++) {
            float rm = fmaxf(fmaxf(s[qi][0], s[qi][1]), fmaxf(s[qi][2], s[qi][3]));
            #pragma unroll
            for (int off = 8; off; off >>= 1)
                rm = fmaxf(rm, __shfl_xor_sync(0xffffffffu, rm, off, 16));
            float mn = fmaxf(m_i[qi], rm);
            float alpha = __expf(m_i[qi] - mn);
            float rs = 0.f;
            #pragma unroll
            for (int ki = 0; ki < 4; ki++) {
                s[qi][ki] = __expf(s[qi][ki] - mn);
                rs += s[qi][ki];
            }
            #pragma unroll
            for (int off = 8; off; off >>= 1)
                rs += __shfl_xor_sync(0xffffffffu, rs, off, 16);
            l_i[qi] = l_i[qi] * alpha + rs;
            m_i[qi] = mn;
            #pragma unroll
            for (int di = 0; di < 4; di++) oacc[qi][di] *= alpha;
        }
        __syncthreads();   // all S reads of KPs complete
        // write P into KPs
        #pragma unroll
        for (int qi = 0; qi < 4; qi++)
            #pragma unroll
            for (int ki = 0; ki < 4; ki++)
                KPs[ty * 4 + qi][tx * 4 + ki] = s[qi][ki];
        __syncthreads();

        // O += P @ V, V in two 32-row halves
        for (int half = 0; half < 2; half++) {
            for (int i = tid; i < 512; i += 256) {
                int row = i >> 4; int c4 = (i & 15) << 2;
                int key = kc * 64 + half * 32 + row;
                float4 v = make_float4(0.f, 0.f, 0.f, 0.f);
                if (key < TOK)
                    v = *(const float4*)(qkv + (size_t)(b * TOK + key) * QKVDIM + 2 * CDIM + h * DHEAD + c4);
                Vs[row][c4 + 0] = v.x; Vs[row][c4 + 1] = v.y;
                Vs[row][c4 + 2] = v.z; Vs[row][c4 + 3] = v.w;
            }
            __syncthreads();
            #pragma unroll 4
            for (int kk = 0; kk < 32; kk++) {
                int k = half * 32 + kk;
                float pv[4];
                #pragma unroll
                for (int qi = 0; qi < 4; qi++) pv[qi] = KPs[ty * 4 + qi][k];
                float4 vv = *(const float4*)&Vs[kk][tx * 4];
                float vvs[4] = {vv.x, vv.y, vv.z, vv.w};
                #pragma unroll
                for (int qi = 0; qi < 4; qi++)
                    #pragma unroll
                    for (int di = 0; di < 4; di++)
                        oacc[qi][di] = fmaf(pv[qi], vvs[di], oacc[qi][di]);
            }
            __syncthreads();
        }
    }

    // store O
    #pragma unroll
    for (int qi = 0; qi < 4; qi++) {
        int q = q0 + ty * 4 + qi;
        if (q < TOK) {
            float inv = 1.0f / l_i[qi];
            float4 r;
            r.x = oacc[qi][0] * inv; r.y = oacc[qi][1] * inv;
            r.z = oacc[qi][2] * inv; r.w = oacc[qi][3] * inv;
            *(float4*)(o + (size_t)(b * TOK + q) * CDIM + h * DHEAD + tx * 4) = r;
        }
    }
}

// ---------------- untokenize: g_t [B,N,C] -> out [B,C,D,H,W] ----------------
__global__ void untok_kernel(float* __restrict__ out) {
    __shared__ float tile[32][33];
    int b  = blockIdx.z;
    int s0 = blockIdx.x * 32;
    int c0 = blockIdx.y * 32;
    int tx = threadIdx.x, ty = threadIdx.y;  // 32 x 8
    #pragma unroll
    for (int r = ty; r < 32; r += 8)
        tile[r][tx] = g_t[(size_t)(b * TOK + s0 + r) * CDIM + c0 + tx];
    __syncthreads();
    #pragma unroll
    for (int r = ty; r < 32; r += 8)
        out[(size_t)(b * CDIM + c0 + r) * TOK + s0 + tx] = tile[tx][r];
}

// ---------------- launch ----------------
extern "C" void kernel_launch(void* const* d_in, const int* in_sizes, int n_in,
                              void* d_out, int out_size) {
    const float* x      = (const float*)d_in[0];
    const float* pos_w  = (const float*)d_in[1];
    const float* pos_b  = (const float*)d_in[2];
    const float* ln1_w  = (const float*)d_in[3];
    const float* ln1_b  = (const float*)d_in[4];
    const float* qkv_w  = (const float*)d_in[5];
    const float* proj_w = (const float*)d_in[6];
    const float* proj_b = (const float*)d_in[7];
    const float* ln2_w  = (const float*)d_in[8];
    const float* ln2_b  = (const float*)d_in[9];
    const float* fc1_w  = (const float*)d_in[10];
    const float* fc1_b  = (const float*)d_in[11];
    const float* fc2_w  = (const float*)d_in[12];
    const float* fc2_b  = (const float*)d_in[13];
    float* out = (float*)d_out;

    float *t, *hbuf, *qkvb, *ob, *mlpb;
    cudaGetSymbolAddress((void**)&t,    g_t);
    cudaGetSymbolAddress((void**)&hbuf, g_h);
    cudaGetSymbolAddress((void**)&qkvb, g_qkv);
    cudaGetSymbolAddress((void**)&ob,   g_o);
    cudaGetSymbolAddress((void**)&mlpb, g_mlp);

    // x + depthwise_conv(x) + pos_b, tokenized into g_t
    conv_pos_kernel<<<BATCH * CDIM, 256>>>(x, pos_w, pos_b);
    // LN1
    ln_kernel<<<TTOK, 256>>>(t, ln1_w, ln1_b, hbuf);
    // QKV = h @ qkv_w^T
    gemm128<0><<<dim3(QKVDIM / 128, TTOK / 128), 256>>>(hbuf, qkv_w, nullptr, nullptr,
                                                        qkvb, TTOK, QKVDIM, CDIM);
    // attention
    attn_kernel<<<dim3((TOK + 63) / 64, BATCH * NHEAD), 256>>>(qkvb, ob);
    // t += o @ proj_w^T + proj_b  (in-place residual)
    gemm128<1><<<dim3(CDIM / 128, TTOK / 128), 256>>>(ob, proj_w, proj_b, t,
                                                      t, TTOK, CDIM, CDIM);
    // LN2
    ln_kernel<<<TTOK, 256>>>(t, ln2_w, ln2_b, hbuf);
    // fc1 + gelu
    gemm128<2><<<dim3(HID / 128, TTOK / 128), 256>>>(hbuf, fc1_w, fc1_b, nullptr,
                                                     mlpb, TTOK, HID, CDIM);
    // t += mlp @ fc2_w^T + fc2_b
    gemm128<1><<<dim3(CDIM / 128, TTOK / 128), 256>>>(mlpb, fc2_w, fc2_b, t,
                                                      t, TTOK, CDIM, HID);
    // back to [B, C, D, H, W]
    untok_kernel<<<dim3(TOK / 32, CDIM / 32, BATCH), dim3(32, 8)>>>(out);
}

// round 2
// speedup vs baseline: 1.9355x; 1.9355x over previous
#include <cuda_runtime.h>
#include <math.h>
#include <stdint.h>

#define TOK    1568          // D*H*W = 8*14*14
#define BATCH  4
#define CDIM   768
#define TTOK   (BATCH*TOK)   // 6272
#define QKVDIM 2304
#define HID    3072
#define NHEAD  12
#define DHEAD  64

// ---------------- scratch ----------------
__device__ float g_t[TTOK * CDIM];
__device__ float g_h[TTOK * CDIM];
__device__ float g_qkv[TTOK * QKVDIM];
__device__ float g_o[TTOK * CDIM];
__device__ float g_mlp[TTOK * HID];

// ---------------- tf32 mma helper ----------------
__device__ __forceinline__ void mma_tf32(float* d, const uint32_t* a, const uint32_t* b) {
    asm volatile(
        "mma.sync.aligned.m16n8k8.row.col.f32.tf32.tf32.f32 "
        "{%0,%1,%2,%3}, {%4,%5,%6,%7}, {%8,%9}, {%0,%1,%2,%3};"
        : "+f"(d[0]), "+f"(d[1]), "+f"(d[2]), "+f"(d[3])
        : "r"(a[0]), "r"(a[1]), "r"(a[2]), "r"(a[3]), "r"(b[0]), "r"(b[1]));
}

// ---------------- conv + bias + residual + tokenize ----------------
__global__ void conv_pos_kernel(const float* __restrict__ x,
                                const float* __restrict__ pw,
                                const float* __restrict__ pb) {
    int bc = blockIdx.x;
    int c  = bc % CDIM;
    int b  = bc / CDIM;
    __shared__ float sx[TOK];
    __shared__ float sw[27];
    int tid = threadIdx.x;
    const float* xs = x + (size_t)bc * TOK;
    for (int i = tid; i < TOK; i += 256) sx[i] = xs[i];
    if (tid < 27) sw[tid] = pw[c * 27 + tid];
    __syncthreads();
    float pbv = pb[c];
    for (int idx = tid; idx < TOK; idx += 256) {
        int d = idx / 196; int r = idx - d * 196;
        int h = r / 14;    int w = r - h * 14;
        float acc = 0.f;
        #pragma unroll
        for (int kd = 0; kd < 3; kd++) {
            int dd = d + kd - 1;
            if (dd < 0 || dd >= 8) continue;
            #pragma unroll
            for (int kh = 0; kh < 3; kh++) {
                int hh = h + kh - 1;
                if (hh < 0 || hh >= 14) continue;
                #pragma unroll
                for (int kw = 0; kw < 3; kw++) {
                    int ww = w + kw - 1;
                    if (ww < 0 || ww >= 14) continue;
                    acc += sw[kd * 9 + kh * 3 + kw] * sx[dd * 196 + hh * 14 + ww];
                }
            }
        }
        g_t[(size_t)(b * TOK + idx) * CDIM + c] = sx[idx] + acc + pbv;
    }
}

// ---------------- LayerNorm ----------------
__global__ void ln_kernel(const float* __restrict__ in, const float* __restrict__ w,
                          const float* __restrict__ bsrc, float* __restrict__ out) {
    int t = blockIdx.x;
    int tid = threadIdx.x;
    const float* row = in + (size_t)t * CDIM;
    float v0 = row[tid], v1 = row[tid + 256], v2 = row[tid + 512];
    float s  = v0 + v1 + v2;
    float sq = v0 * v0 + v1 * v1 + v2 * v2;
    #pragma unroll
    for (int off = 16; off; off >>= 1) {
        s  += __shfl_xor_sync(0xffffffffu, s,  off);
        sq += __shfl_xor_sync(0xffffffffu, sq, off);
    }
    __shared__ float ss[8], ssq[8];
    int wid = tid >> 5, lid = tid & 31;
    if (lid == 0) { ss[wid] = s; ssq[wid] = sq; }
    __syncthreads();
    if (tid < 32) {
        s  = (lid < 8) ? ss[lid]  : 0.f;
        sq = (lid < 8) ? ssq[lid] : 0.f;
        #pragma unroll
        for (int off = 4; off; off >>= 1) {
            s  += __shfl_xor_sync(0xffffffffu, s,  off);
            sq += __shfl_xor_sync(0xffffffffu, sq, off);
        }
        if (lid == 0) { ss[0] = s; ssq[0] = sq; }
    }
    __syncthreads();
    float mean = ss[0] * (1.f / CDIM);
    float var  = ssq[0] * (1.f / CDIM) - mean * mean;
    float rs   = rsqrtf(var + 1e-5f);
    float* orow = out + (size_t)t * CDIM;
    orow[tid]       = (v0 - mean) * rs * w[tid]       + bsrc[tid];
    orow[tid + 256] = (v1 - mean) * rs * w[tid + 256] + bsrc[tid + 256];
    orow[tid + 512] = (v2 - mean) * rs * w[tid + 512] + bsrc[tid + 512];
}

// ---------------- tf32 tensor-core GEMM ----------------
// C[M,N] = A[M,K] @ B[N,K]^T (+epilogue). Block 128x128, BK=16, 256 thr (8 warps).
// Warp tile 64x32: wm=warp>>2 (2), wn=warp&3 (4). m-tiles 4 (16), n-tiles 4 (8).
// Smem k-major, stride 136 (== 8 mod 32): conflict-free STS transpose + fragment LDS.
__device__ __forceinline__ float gelu_exact(float v) {
    return 0.5f * v * (1.f + erff(v * 0.70710678118654752f));
}

template <int MODE>
__global__ void __launch_bounds__(256)
gemm_tc(const float* __restrict__ A, const float* __restrict__ B,
        const float* __restrict__ bias, const float* __restrict__ resid,
        float* __restrict__ C, int M, int N, int K) {
    __shared__ __align__(16) float As[16 * 136];
    __shared__ __align__(16) float Bs[16 * 136];
    int tid = threadIdx.x;
    int lane = tid & 31, warp = tid >> 5;
    int wm = warp >> 2, wn = warp & 3;
    int m0 = blockIdx.y << 7, n0 = blockIdx.x << 7;

    int ar  = tid & 127;     // row within tile
    int akq = tid >> 7;      // base k-quad (0..1); quads akq and akq+2

    const float* Ag = A + (size_t)(m0 + ar) * K;
    const float* Bg = B + (size_t)(n0 + ar) * K;

    float acc[4][4][4];
    #pragma unroll
    for (int mi = 0; mi < 4; mi++)
        #pragma unroll
        for (int ni = 0; ni < 4; ni++)
            #pragma unroll
            for (int r = 0; r < 4; r++) acc[mi][ni][r] = 0.f;

    int nch = K >> 4;
    float4 pa[2], pb[2];
    #pragma unroll
    for (int i = 0; i < 2; i++) {
        pa[i] = *(const float4*)(Ag + (akq + 2 * i) * 4);
        pb[i] = *(const float4*)(Bg + (akq + 2 * i) * 4);
    }

    for (int ch = 0; ch < nch; ch++) {
        __syncthreads();
        #pragma unroll
        for (int i = 0; i < 2; i++) {
            int kq = akq + 2 * i;
            As[(kq * 4 + 0) * 136 + ar] = pa[i].x;
            As[(kq * 4 + 1) * 136 + ar] = pa[i].y;
            As[(kq * 4 + 2) * 136 + ar] = pa[i].z;
            As[(kq * 4 + 3) * 136 + ar] = pa[i].w;
            Bs[(kq * 4 + 0) * 136 + ar] = pb[i].x;
            Bs[(kq * 4 + 1) * 136 + ar] = pb[i].y;
            Bs[(kq * 4 + 2) * 136 + ar] = pb[i].z;
            Bs[(kq * 4 + 3) * 136 + ar] = pb[i].w;
        }
        __syncthreads();
        if (ch + 1 < nch) {
            int k0 = (ch + 1) << 4;
            #pragma unroll
            for (int i = 0; i < 2; i++) {
                pa[i] = *(const float4*)(Ag + k0 + (akq + 2 * i) * 4);
                pb[i] = *(const float4*)(Bg + k0 + (akq + 2 * i) * 4);
            }
        }
        #pragma unroll
        for (int kb = 0; kb < 16; kb += 8) {
            int kk = kb + (lane & 3);
            uint32_t af[4][4], bf[4][2];
            int mbase = wm * 64 + (lane >> 2);
            #pragma unroll
            for (int mi = 0; mi < 4; mi++) {
                int m = mbase + mi * 16;
                af[mi][0] = __float_as_uint(As[kk * 136 + m]);
                af[mi][1] = __float_as_uint(As[kk * 136 + m + 8]);
                af[mi][2] = __float_as_uint(As[(kk + 4) * 136 + m]);
                af[mi][3] = __float_as_uint(As[(kk + 4) * 136 + m + 8]);
            }
            int nbase = wn * 32 + (lane >> 2);
            #pragma unroll
            for (int ni = 0; ni < 4; ni++) {
                int n = nbase + ni * 8;
                bf[ni][0] = __float_as_uint(Bs[kk * 136 + n]);
                bf[ni][1] = __float_as_uint(Bs[(kk + 4) * 136 + n]);
            }
            #pragma unroll
            for (int mi = 0; mi < 4; mi++)
                #pragma unroll
                for (int ni = 0; ni < 4; ni++)
                    mma_tf32(acc[mi][ni], af[mi], bf[ni]);
        }
    }

    // epilogue
    int r0 = lane >> 2, cq = (lane & 3) * 2;
    #pragma unroll
    for (int mi = 0; mi < 4; mi++) {
        int rowA = m0 + wm * 64 + mi * 16 + r0;
        int rowB = rowA + 8;
        #pragma unroll
        for (int ni = 0; ni < 4; ni++) {
            int col = n0 + wn * 32 + ni * 8 + cq;
            float2 va = make_float2(acc[mi][ni][0], acc[mi][ni][1]);
            float2 vb = make_float2(acc[mi][ni][2], acc[mi][ni][3]);
            if (MODE == 1) {
                float2 bv = *(const float2*)(bias + col);
                float2 ra = *(const float2*)(resid + (size_t)rowA * N + col);
                float2 rb = *(const float2*)(resid + (size_t)rowB * N + col);
                va.x += bv.x + ra.x; va.y += bv.y + ra.y;
                vb.x += bv.x + rb.x; vb.y += bv.y + rb.y;
            } else if (MODE == 2) {
                float2 bv = *(const float2*)(bias + col);
                va.x = gelu_exact(va.x + bv.x); va.y = gelu_exact(va.y + bv.y);
                vb.x = gelu_exact(vb.x + bv.x); vb.y = gelu_exact(vb.y + bv.y);
            }
            *(float2*)(C + (size_t)rowA * N + col) = va;
            *(float2*)(C + (size_t)rowB * N + col) = vb;
        }
    }
}

// ---------------- tf32 tensor-core flash attention ----------------
// Block: 128 thr (4 warps), 64 queries; warp owns 16 query rows. 25 key chunks of 64.
// KP buffer (stride 68) holds K then is reused for P; Vs (stride 72).
__global__ void __launch_bounds__(128)
attn_tc(const float* __restrict__ qkv, float* __restrict__ o) {
    __shared__ __align__(16) float KP[64 * 68];
    __shared__ __align__(16) float Vs[64 * 72];
    int tid = threadIdx.x, lane = tid & 31, warp = tid >> 5;
    int bh = blockIdx.y;
    int b = bh / NHEAD, h = bh % NHEAD;
    int q0 = blockIdx.x * 64;
    const float* base = qkv + (size_t)b * TOK * QKVDIM + h * DHEAD;

    int r0 = lane >> 2, kq = lane & 3;
    // Q fragments (scale folded): rows warp*16 + r0 (+8), k = kt*8 + kq (+4)
    uint32_t qf[8][4];
    {
        int qa = q0 + warp * 16 + r0;
        int qb = qa + 8;
        const float* pa = base + (size_t)qa * QKVDIM;
        const float* pb = base + (size_t)qb * QKVDIM;
        bool va = qa < TOK, vb = qb < TOK;
        #pragma unroll
        for (int kt = 0; kt < 8; kt++) {
            int k = kt * 8 + kq;
            qf[kt][0] = va ? __float_as_uint(pa[k] * 0.125f) : 0u;
            qf[kt][1] = vb ? __float_as_uint(pb[k] * 0.125f) : 0u;
            qf[kt][2] = va ? __float_as_uint(pa[k + 4] * 0.125f) : 0u;
            qf[kt][3] = vb ? __float_as_uint(pb[k + 4] * 0.125f) : 0u;
        }
    }

    float oacc[8][4];
    #pragma unroll
    for (int nt = 0; nt < 8; nt++)
        #pragma unroll
        for (int r = 0; r < 4; r++) oacc[nt][r] = 0.f;
    float mi0 = -1e30f, mi1 = -1e30f, li0 = 0.f, li1 = 0.f;

    for (int kc = 0; kc < 25; kc++) {
        __syncthreads();
        // load K and V chunk
        #pragma unroll
        for (int i = 0; i < 8; i++) {
            int q = tid + i * 128;
            int key = q >> 4;
            int d4  = (q & 15) << 2;
            int kg = kc * 64 + key;
            float4 kv = make_float4(0.f, 0.f, 0.f, 0.f);
            float4 vv = make_float4(0.f, 0.f, 0.f, 0.f);
            if (kg < TOK) {
                kv = *(const float4*)(base + (size_t)kg * QKVDIM + CDIM + d4);
                vv = *(const float4*)(base + (size_t)kg * QKVDIM + 2 * CDIM + d4);
            }
            *(float4*)&KP[key * 68 + d4] = kv;
            *(float4*)&Vs[key * 72 + d4] = vv;
        }
        __syncthreads();

        // S = Q @ K^T
        float s[8][4];
        #pragma unroll
        for (int ni = 0; ni < 8; ni++)
            #pragma unroll
            for (int r = 0; r < 4; r++) s[ni][r] = 0.f;
        #pragma unroll
        for (int kt = 0; kt < 8; kt++) {
            int kk = kt * 8 + kq;
            #pragma unroll
            for (int ni = 0; ni < 8; ni++) {
                int n = ni * 8 + r0;
                uint32_t bf[2];
                bf[0] = __float_as_uint(KP[n * 68 + kk]);
                bf[1] = __float_as_uint(KP[n * 68 + kk + 4]);
                mma_tf32(s[ni], qf[kt], bf);
            }
        }
        // mask OOB keys (only last chunk: keys 1536..1599)
        if (kc == 24) {
            #pragma unroll
            for (int ni = 0; ni < 8; ni++) {
                int c = kc * 64 + ni * 8 + kq * 2;
                if (c >= TOK)     { s[ni][0] = -1e30f; s[ni][2] = -1e30f; }
                if (c + 1 >= TOK) { s[ni][1] = -1e30f; s[ni][3] = -1e30f; }
            }
        }
        // online softmax: row r0 -> regs {0,1}, row r0+8 -> regs {2,3}
        float mr0 = -1e30f, mr1 = -1e30f;
        #pragma unroll
        for (int ni = 0; ni < 8; ni++) {
            mr0 = fmaxf(mr0, fmaxf(s[ni][0], s[ni][1]));
            mr1 = fmaxf(mr1, fmaxf(s[ni][2], s[ni][3]));
        }
        mr0 = fmaxf(mr0, __shfl_xor_sync(0xffffffffu, mr0, 1));
        mr0 = fmaxf(mr0, __shfl_xor_sync(0xffffffffu, mr0, 2));
        mr1 = fmaxf(mr1, __shfl_xor_sync(0xffffffffu, mr1, 1));
        mr1 = fmaxf(mr1, __shfl_xor_sync(0xffffffffu, mr1, 2));
        float mn0 = fmaxf(mi0, mr0), mn1 = fmaxf(mi1, mr1);
        float a0 = __expf(mi0 - mn0), a1 = __expf(mi1 - mn1);
        float sum0 = 0.f, sum1 = 0.f;
        #pragma unroll
        for (int ni = 0; ni < 8; ni++) {
            s[ni][0] = __expf(s[ni][0] - mn0);
            s[ni][1] = __expf(s[ni][1] - mn0);
            s[ni][2] = __expf(s[ni][2] - mn1);
            s[ni][3] = __expf(s[ni][3] - mn1);
            sum0 += s[ni][0] + s[ni][1];
            sum1 += s[ni][2] + s[ni][3];
        }
        sum0 += __shfl_xor_sync(0xffffffffu, sum0, 1);
        sum0 += __shfl_xor_sync(0xffffffffu, sum0, 2);
        sum1 += __shfl_xor_sync(0xffffffffu, sum1, 1);
        sum1 += __shfl_xor_sync(0xffffffffu, sum1, 2);
        li0 = li0 * a0 + sum0; li1 = li1 * a1 + sum1;
        mi0 = mn0; mi1 = mn1;
        #pragma unroll
        for (int nt = 0; nt < 8; nt++) {
            oacc[nt][0] *= a0; oacc[nt][1] *= a0;
            oacc[nt][2] *= a1; oacc[nt][3] *= a1;
        }
        __syncthreads();   // all warps done reading K from KP
        // write P into KP (each warp its own 16 rows)
        {
            int prow = warp * 16 + r0;
            #pragma unroll
            for (int ni = 0; ni < 8; ni++) {
                int col = ni * 8 + kq * 2;
                *(float2*)&KP[prow * 68 + col]       = make_float2(s[ni][0], s[ni][1]);
                *(float2*)&KP[(prow + 8) * 68 + col] = make_float2(s[ni][2], s[ni][3]);
            }
        }
        __syncwarp();
        // O += P @ V
        #pragma unroll
        for (int kt = 0; kt < 8; kt++) {
            int kk = kt * 8 + kq;
            uint32_t pf[4];
            int prow = warp * 16 + r0;
            pf[0] = __float_as_uint(KP[prow * 68 + kk]);
            pf[1] = __float_as_uint(KP[(prow + 8) * 68 + kk]);
            pf[2] = __float_as_uint(KP[prow * 68 + kk + 4]);
            pf[3] = __float_as_uint(KP[(prow + 8) * 68 + kk + 4]);
            #pragma unroll
            for (int nt = 0; nt < 8; nt++) {
                int n = nt * 8 + r0;
                uint32_t bf[2];
                bf[0] = __float_as_uint(Vs[kk * 72 + n]);
                bf[1] = __float_as_uint(Vs[(kk + 4) * 72 + n]);
                mma_tf32(oacc[nt], pf, bf);
            }
        }
    }

    // store O
    int qa = q0 + warp * 16 + r0;
    int qb = qa + 8;
    float inv0 = 1.f / li0, inv1 = 1.f / li1;
    #pragma unroll
    for (int nt = 0; nt < 8; nt++) {
        int col = h * DHEAD + nt * 8 + kq * 2;
        if (qa < TOK)
            *(float2*)(o + (size_t)(b * TOK + qa) * CDIM + col) =
                make_float2(oacc[nt][0] * inv0, oacc[nt][1] * inv0);
        if (qb < TOK)
            *(float2*)(o + (size_t)(b * TOK + qb) * CDIM + col) =
                make_float2(oacc[nt][2] * inv1, oacc[nt][3] * inv1);
    }
}

// ---------------- untokenize ----------------
__global__ void untok_kernel(float* __restrict__ out) {
    __shared__ float tile[32][33];
    int b  = blockIdx.z;
    int s0 = blockIdx.x * 32;
    int c0 = blockIdx.y * 32;
    int tx = threadIdx.x, ty = threadIdx.y;
    #pragma unroll
    for (int r = ty; r < 32; r += 8)
        tile[r][tx] = g_t[(size_t)(b * TOK + s0 + r) * CDIM + c0 + tx];
    __syncthreads();
    #pragma unroll
    for (int r = ty; r < 32; r += 8)
        out[(size_t)(b * CDIM + c0 + r) * TOK + s0 + tx] = tile[tx][r];
}

// ---------------- launch ----------------
extern "C" void kernel_launch(void* const* d_in, const int* in_sizes, int n_in,
                              void* d_out, int out_size) {
    const float* x      = (const float*)d_in[0];
    const float* pos_w  = (const float*)d_in[1];
    const float* pos_b  = (const float*)d_in[2];
    const float* ln1_w  = (const float*)d_in[3];
    const float* ln1_b  = (const float*)d_in[4];
    const float* qkv_w  = (const float*)d_in[5];
    const float* proj_w = (const float*)d_in[6];
    const float* proj_b = (const float*)d_in[7];
    const float* ln2_w  = (const float*)d_in[8];
    const float* ln2_b  = (const float*)d_in[9];
    const float* fc1_w  = (const float*)d_in[10];
    const float* fc1_b  = (const float*)d_in[11];
    const float* fc2_w  = (const float*)d_in[12];
    const float* fc2_b  = (const float*)d_in[13];
    float* out = (float*)d_out;

    float *t, *hbuf, *qkvb, *ob, *mlpb;
    cudaGetSymbolAddress((void**)&t,    g_t);
    cudaGetSymbolAddress((void**)&hbuf, g_h);
    cudaGetSymbolAddress((void**)&qkvb, g_qkv);
    cudaGetSymbolAddress((void**)&ob,   g_o);
    cudaGetSymbolAddress((void**)&mlpb, g_mlp);

    conv_pos_kernel<<<BATCH * CDIM, 256>>>(x, pos_w, pos_b);
    ln_kernel<<<TTOK, 256>>>(t, ln1_w, ln1_b, hbuf);
    gemm_tc<0><<<dim3(QKVDIM / 128, TTOK / 128), 256>>>(hbuf, qkv_w, nullptr, nullptr,
                                                        qkvb, TTOK, QKVDIM, CDIM);
    attn_tc<<<dim3(25, BATCH * NHEAD), 128>>>(qkvb, ob);
    gemm_tc<1><<<dim3(CDIM / 128, TTOK / 128), 256>>>(ob, proj_w, proj_b, t,
                                                      t, TTOK, CDIM, CDIM);
    ln_kernel<<<TTOK, 256>>>(t, ln2_w, ln2_b, hbuf);
    gemm_tc<2><<<dim3(HID / 128, TTOK / 128), 256>>>(hbuf, fc1_w, fc1_b, nullptr,
                                                     mlpb, TTOK, HID, CDIM);
    gemm_tc<1><<<dim3(CDIM / 128, TTOK / 128), 256>>>(mlpb, fc2_w, fc2_b, t,
                                                      t, TTOK, CDIM, HID);
    untok_kernel<<<dim3(TOK / 32, CDIM / 32, BATCH), dim3(32, 8)>>>(out);
}